// round 9
// baseline (speedup 1.0000x reference)
#include <cuda_runtime.h>

#define IN_DIM   8192
#define OUT_DIM  8192
#define TPB      256                   // 8 warps per block, 1 row per warp
#define WPB      (TPB / 32)
#define LVPT     (IN_DIM / 4 / 32)     // float4 per lane per row = 64
#define THRESH   50.0f

__global__ __launch_bounds__(TPB)
void snn_warprow_kernel(const float* __restrict__ spike_input,
                        const float* __restrict__ states,
                        const float* __restrict__ v_mem,
                        const float* __restrict__ v_th,
                        const float* __restrict__ elig,
                        const float* __restrict__ noise,
                        float* __restrict__ out)
{
    const int lane = threadIdx.x & 31;
    const int row  = blockIdx.x * WPB + (threadIdx.x >> 5);

    const float4* sp4  = reinterpret_cast<const float4*>(spike_input);
    const float4* st4  = reinterpret_cast<const float4*>(states + (size_t)row * IN_DIM);
    const float4* el4  = reinterpret_cast<const float4*>(elig   + (size_t)row * IN_DIM);
    float4*       out4 = reinterpret_cast<float4*>(out + 3 * (size_t)OUT_DIM + (size_t)row * IN_DIM);

    // ---- phase 1: GEMV dot product, warp-private (no barriers anywhere) ----
    float acc = 0.0f;
    #pragma unroll 8
    for (int it = 0; it < LVPT; ++it) {
        const int i = it * 32 + lane;
        float4 s  = __ldcs(&st4[i]);
        float4 sp = __ldg(&sp4[i]);
        if (s.x > THRESH) acc += sp.x;
        if (s.y > THRESH) acc += sp.y;
        if (s.z > THRESH) acc += sp.z;
        if (s.w > THRESH) acc += sp.w;
    }

    // ---- warp reduction (5 shuffles, no smem, no BAR) ----
    #pragma unroll
    for (int off = 16; off > 0; off >>= 1)
        acc += __shfl_xor_sync(0xFFFFFFFFu, acc, off);

    // ---- neuron dynamics on lane 0, broadcast spike via shuffle ----
    float spk;
    if (lane == 0) {
        const float vth   = v_th[row];
        const float v_new = v_mem[row] * 0.8f + acc + noise[row];
        spk = (v_new >= vth) ? 1.0f : 0.0f;

        // outputs: [spikes | v_mem_new | v_th_new | elig_new]
        out[row]           = spk;
        out[OUT_DIM + row] = v_new * (1.0f - spk) * 0.2f;
        float vth_new = vth + (spk - 0.05f) * 0.1f;
        out[2 * OUT_DIM + row] = fminf(fmaxf(vth_new, 0.5f), 10.0f);
    }
    spk = __shfl_sync(0xFFFFFFFFu, spk, 0);

    // ---- phase 2: eligibility trace update, warp-private ----
    #pragma unroll 8
    for (int it = 0; it < LVPT; ++it) {
        const int i = it * 32 + lane;
        float4 e  = __ldcs(&el4[i]);
        float4 sp = __ldg(&sp4[i]);        // L1/L2 hit (same addrs as phase 1)
        float4 r;
        r.x = fminf(fmaxf(fmaf(e.x, 0.95f, spk * sp.x), 0.0f), 5.0f);
        r.y = fminf(fmaxf(fmaf(e.y, 0.95f, spk * sp.y), 0.0f), 5.0f);
        r.z = fminf(fmaxf(fmaf(e.z, 0.95f, spk * sp.z), 0.0f), 5.0f);
        r.w = fminf(fmaxf(fmaf(e.w, 0.95f, spk * sp.w), 0.0f), 5.0f);
        __stcs(&out4[i], r);
    }
}

extern "C" void kernel_launch(void* const* d_in, const int* in_sizes, int n_in,
                              void* d_out, int out_size)
{
    const float* spike_input = (const float*)d_in[0];
    const float* states      = (const float*)d_in[1];
    const float* v_mem       = (const float*)d_in[2];
    const float* v_th        = (const float*)d_in[3];
    const float* elig        = (const float*)d_in[4];
    const float* noise       = (const float*)d_in[5];
    float* out = (float*)d_out;

    snn_warprow_kernel<<<OUT_DIM / WPB, TPB>>>(spike_input, states, v_mem, v_th,
                                               elig, noise, out);
}

// round 10
// speedup vs baseline: 1.1979x; 1.1979x over previous
#include <cuda_runtime.h>

#define IN_DIM   8192
#define OUT_DIM  8192
#define TPB      256
#define VPT      (IN_DIM / 4 / TPB)   // float4 per thread per row = 8
#define THRESH   50.0f

__global__ __launch_bounds__(TPB)
void snn_fused_kernel(const float* __restrict__ spike_input,
                      const float* __restrict__ states,
                      const float* __restrict__ v_mem,
                      const float* __restrict__ v_th,
                      const float* __restrict__ elig,
                      const float* __restrict__ noise,
                      float* __restrict__ out)
{
    __shared__ float s_warp[TPB / 32];
    __shared__ float s_spk;

    const int row = blockIdx.x;
    const int tid = threadIdx.x;

    const float4* sp4  = reinterpret_cast<const float4*>(spike_input);
    const float4* st4  = reinterpret_cast<const float4*>(states + (size_t)row * IN_DIM);
    const float4* el4  = reinterpret_cast<const float4*>(elig   + (size_t)row * IN_DIM);
    float4*       out4 = reinterpret_cast<float4*>(out + 3 * (size_t)OUT_DIM + (size_t)row * IN_DIM);

    // ---- phase 1: binary-weight GEMV dot product ----
    // Batch the states loads up front (max MLP), then the spike loads
    // (32 KB, L1/L2-resident), then consume.
    float4 s[VPT], sp[VPT];
    #pragma unroll
    for (int it = 0; it < VPT; ++it)
        s[it] = __ldcs(&st4[it * TPB + tid]);
    #pragma unroll
    for (int it = 0; it < VPT; ++it)
        sp[it] = __ldg(&sp4[it * TPB + tid]);

    float acc = 0.0f;
    #pragma unroll
    for (int it = 0; it < VPT; ++it) {
        if (s[it].x > THRESH) acc += sp[it].x;
        if (s[it].y > THRESH) acc += sp[it].y;
        if (s[it].z > THRESH) acc += sp[it].z;
        if (s[it].w > THRESH) acc += sp[it].w;
    }

    // ---- block reduction ----
    #pragma unroll
    for (int off = 16; off > 0; off >>= 1)
        acc += __shfl_xor_sync(0xFFFFFFFFu, acc, off);
    if ((tid & 31) == 0) s_warp[tid >> 5] = acc;
    __syncthreads();

    if (tid == 0) {
        float total = 0.0f;
        #pragma unroll
        for (int w = 0; w < TPB / 32; ++w) total += s_warp[w];

        const float vth   = v_th[row];
        const float v_new = v_mem[row] * 0.8f + total + noise[row];
        const float spk   = (v_new >= vth) ? 1.0f : 0.0f;

        // outputs: [spikes | v_mem_new | v_th_new | elig_new]
        out[row]           = spk;
        out[OUT_DIM + row] = v_new * (1.0f - spk) * 0.2f;
        float vth_new = vth + (spk - 0.05f) * 0.1f;
        out[2 * OUT_DIM + row] = fminf(fmaxf(vth_new, 0.5f), 10.0f);

        s_spk = spk;
    }
    __syncthreads();

    // ---- phase 2: eligibility trace update (spike vector reused from regs) ----
    const float spk = s_spk;
    #pragma unroll
    for (int it = 0; it < VPT; ++it) {
        const int i = it * TPB + tid;
        float4 e = __ldcs(&el4[i]);
        float4 r;
        r.x = fminf(fmaxf(fmaf(e.x, 0.95f, spk * sp[it].x), 0.0f), 5.0f);
        r.y = fminf(fmaxf(fmaf(e.y, 0.95f, spk * sp[it].y), 0.0f), 5.0f);
        r.z = fminf(fmaxf(fmaf(e.z, 0.95f, spk * sp[it].z), 0.0f), 5.0f);
        r.w = fminf(fmaxf(fmaf(e.w, 0.95f, spk * sp[it].w), 0.0f), 5.0f);
        __stcs(&out4[i], r);
    }
}

extern "C" void kernel_launch(void* const* d_in, const int* in_sizes, int n_in,
                              void* d_out, int out_size)
{
    const float* spike_input = (const float*)d_in[0];
    const float* states      = (const float*)d_in[1];
    const float* v_mem       = (const float*)d_in[2];
    const float* v_th        = (const float*)d_in[3];
    const float* elig        = (const float*)d_in[4];
    const float* noise       = (const float*)d_in[5];
    float* out = (float*)d_out;

    snn_fused_kernel<<<OUT_DIM, TPB>>>(spike_input, states, v_mem, v_th,
                                       elig, noise, out);
}

// round 11
// speedup vs baseline: 1.4137x; 1.1802x over previous
#include <cuda_runtime.h>

#define IN_DIM  8192
#define OUT_DIM 8192
#define TPB     256
#define THRESH  50.0f

__global__ __launch_bounds__(TPB, 4)
void snn_fused_kernel(const float* __restrict__ spike_input,
                      const float* __restrict__ states,
                      const float* __restrict__ v_mem,
                      const float* __restrict__ v_th,
                      const float* __restrict__ elig,
                      const float* __restrict__ noise,
                      float* __restrict__ out)
{
    __shared__ float s_spike[IN_DIM];        // 32 KB: spike_input staged once
    __shared__ float s_warp[TPB / 32];
    __shared__ float s_spk_bcast;

    const int row = blockIdx.x;
    const int tid = threadIdx.x;

    // ---- stage spike_input into shared (vectorized) ----
    const float4* sp4 = reinterpret_cast<const float4*>(spike_input);
    float4* ss4 = reinterpret_cast<float4*>(s_spike);
    #pragma unroll
    for (int it = 0; it < IN_DIM / 4 / TPB; ++it)
        ss4[it * TPB + tid] = sp4[it * TPB + tid];
    __syncthreads();

    // ---- phase 1: binary-weight GEMV row dot product ----
    const float4* st4 = reinterpret_cast<const float4*>(states + (size_t)row * IN_DIM);
    float acc = 0.0f;
    #pragma unroll
    for (int it = 0; it < IN_DIM / 4 / TPB; ++it) {
        const int i = it * TPB + tid;
        float4 s  = st4[i];
        float4 sp = ss4[i];
        // w = (state > 50) ? 1 : 0 ; acc += w * spike (spike is 0/1)
        if (s.x > THRESH) acc += sp.x;
        if (s.y > THRESH) acc += sp.y;
        if (s.z > THRESH) acc += sp.z;
        if (s.w > THRESH) acc += sp.w;
    }

    // warp reduce
    #pragma unroll
    for (int off = 16; off > 0; off >>= 1)
        acc += __shfl_xor_sync(0xFFFFFFFFu, acc, off);
    if ((tid & 31) == 0) s_warp[tid >> 5] = acc;
    __syncthreads();

    // ---- per-row scalar dynamics (thread 0) ----
    if (tid == 0) {
        float total = 0.0f;
        #pragma unroll
        for (int w = 0; w < TPB / 32; ++w) total += s_warp[w];

        const float vth   = v_th[row];
        const float v_new = v_mem[row] * 0.8f + total + noise[row];
        const float spk   = (v_new >= vth) ? 1.0f : 0.0f;

        // outputs: [spikes | v_mem_new | v_th_new | elig_new]
        out[row]               = spk;
        out[OUT_DIM + row]     = v_new * (1.0f - spk) * 0.2f;
        float vth_new = vth + (spk - 0.05f) * 0.1f;
        vth_new = fminf(fmaxf(vth_new, 0.5f), 10.0f);
        out[2 * OUT_DIM + row] = vth_new;

        s_spk_bcast = spk;
    }
    __syncthreads();

    // ---- phase 2: eligibility trace row update ----
    const float spk = s_spk_bcast;
    const float4* el4 = reinterpret_cast<const float4*>(elig + (size_t)row * IN_DIM);
    float4* out4 = reinterpret_cast<float4*>(out + 3 * (size_t)OUT_DIM + (size_t)row * IN_DIM);
    #pragma unroll
    for (int it = 0; it < IN_DIM / 4 / TPB; ++it) {
        const int i = it * TPB + tid;
        float4 e  = el4[i];
        float4 sp = ss4[i];
        e.x = fminf(fmaxf(fmaf(e.x, 0.95f, spk * sp.x), 0.0f), 5.0f);
        e.y = fminf(fmaxf(fmaf(e.y, 0.95f, spk * sp.y), 0.0f), 5.0f);
        e.z = fminf(fmaxf(fmaf(e.z, 0.95f, spk * sp.z), 0.0f), 5.0f);
        e.w = fminf(fmaxf(fmaf(e.w, 0.95f, spk * sp.w), 0.0f), 5.0f);
        out4[i] = e;
    }
}

extern "C" void kernel_launch(void* const* d_in, const int* in_sizes, int n_in,
                              void* d_out, int out_size)
{
    const float* spike_input = (const float*)d_in[0];
    const float* states      = (const float*)d_in[1];
    const float* v_mem       = (const float*)d_in[2];
    const float* v_th        = (const float*)d_in[3];
    const float* elig        = (const float*)d_in[4];
    const float* noise       = (const float*)d_in[5];
    float* out = (float*)d_out;

    snn_fused_kernel<<<OUT_DIM, TPB>>>(spike_input, states, v_mem, v_th,
                                       elig, noise, out);
}